// round 2
// baseline (speedup 1.0000x reference)
#include <cuda_runtime.h>

#define BB 8
#define CC 96
#define C3 288
#define HH 192
#define WW 192
#define HWP (HH*WW)
#define NH 3
#define HD 32
#define TILE 64
#define NTILE (HWP/TILE)
#define NCHUNK 16
#define CHUNK (HWP/NCHUNK)
#define ST 64   // smem row stride for k1/k5 tiles

typedef unsigned long long u64;

__device__ float g_qkv [(size_t)BB*C3*HWP];
__device__ float g_qkvd[(size_t)BB*C3*HWP];
__device__ float g_Sp  [NCHUNK*BB*NH*HD*HD];
__device__ float g_sqp [NCHUNK*BB*192];
__device__ float g_A   [BB*NH*HD*HD];

__device__ __forceinline__ u64 bcast2(float a) {
    u64 r; asm("mov.b64 %0, {%1, %1};" : "=l"(r) : "f"(a)); return r;
}
__device__ __forceinline__ void fma2(u64& d, u64 a, u64 b) {
    asm("fma.rn.f32x2 %0, %1, %2, %0;" : "+l"(d) : "l"(a), "l"(b));
}
__device__ __forceinline__ float2 unpk(u64 v) {
    float2 r; asm("mov.b64 {%0, %1}, %2;" : "=f"(r.x), "=f"(r.y) : "l"(v)); return r;
}
__device__ __forceinline__ float f4get(const float4& v, int k) {
    return k == 0 ? v.x : (k == 1 ? v.y : (k == 2 ? v.z : v.w));
}

// 3 output rows (w, w+96, w+192 offsets handled by caller), 8 cols, K=96.
// smi layout [k][t], stride ST. All lanes read same smem row -> broadcast.
__device__ __forceinline__ void gemm_3row(
    const float* __restrict__ w, const float* __restrict__ smi,
    int t0, u64 acc[3][4])
{
    #pragma unroll 2
    for (int k = 0; k < 96; k += 4) {
        float4 wA = *(const float4*)(w + k);
        float4 wB = *(const float4*)(w + 96 + k);
        float4 wC = *(const float4*)(w + 192 + k);
        #pragma unroll
        for (int kk = 0; kk < 4; kk++) {
            const float* sp = smi + (k + kk)*ST + t0;
            ulonglong2 v01 = *(const ulonglong2*)sp;
            ulonglong2 v23 = *(const ulonglong2*)(sp + 4);
            u64 a2 = bcast2(f4get(wA, kk));
            u64 b2 = bcast2(f4get(wB, kk));
            u64 c2 = bcast2(f4get(wC, kk));
            fma2(acc[0][0], a2, v01.x); fma2(acc[0][1], a2, v01.y);
            fma2(acc[0][2], a2, v23.x); fma2(acc[0][3], a2, v23.y);
            fma2(acc[1][0], b2, v01.x); fma2(acc[1][1], b2, v01.y);
            fma2(acc[1][2], b2, v23.x); fma2(acc[1][3], b2, v23.y);
            fma2(acc[2][0], c2, v01.x); fma2(acc[2][1], c2, v01.y);
            fma2(acc[2][2], c2, v23.x); fma2(acc[2][3], c2, v23.y);
        }
    }
}

// ============ K1: LN1 + qkv 1x1 (96 -> 288) ============
__global__ void __launch_bounds__(256) k1_ln_qkv(
    const float* __restrict__ x,    const float* __restrict__ ln1w,
    const float* __restrict__ ln1b, const float* __restrict__ qkvw,
    const float* __restrict__ qkvb)
{
    __shared__ __align__(16) float xs[96*ST];
    int b  = blockIdx.x / NTILE;
    int p0 = (blockIdx.x % NTILE) * TILE;
    int tid = threadIdx.x;

    const float* xb = x + (size_t)b*CC*HWP + p0;
    for (int idx = tid; idx < 96*TILE; idx += 256) {
        int c = idx >> 6, t = idx & 63;
        xs[c*ST + t] = xb[(size_t)c*HWP + t];
    }
    __syncthreads();
    if (tid < TILE) {
        float s = 0.f, s2 = 0.f;
        #pragma unroll
        for (int c = 0; c < 96; c++) { float v = xs[c*ST + tid]; s += v; s2 += v*v; }
        float mu  = s * (1.0f/96.0f);
        float var = fmaxf(s2 * (1.0f/96.0f) - mu*mu, 0.f);
        float rs  = rsqrtf(var + 1e-6f);
        #pragma unroll
        for (int c = 0; c < 96; c++) {
            float v = xs[c*ST + tid];
            xs[c*ST + tid] = (v - mu) * rs * ln1w[c] + ln1b[c];
        }
    }
    __syncthreads();

    int rg = tid >> 3, cg = tid & 7;
    int t0 = cg * 8;
    float* outp = g_qkv + (size_t)b*C3*HWP + p0;
    #pragma unroll 1
    for (int grp = 0; grp < 3; grp++) {
        int row0 = grp*96 + rg*3;
        u64 acc[3][4];
        #pragma unroll
        for (int r = 0; r < 3; r++)
            #pragma unroll
            for (int c = 0; c < 4; c++) acc[r][c] = 0ull;
        gemm_3row(qkvw + (size_t)row0*96, xs, t0, acc);
        #pragma unroll
        for (int r = 0; r < 3; r++) {
            int row = row0 + r;
            float bias = qkvb[row];
            float4 o0, o1; float2 p;
            p = unpk(acc[r][0]); o0.x = p.x + bias; o0.y = p.y + bias;
            p = unpk(acc[r][1]); o0.z = p.x + bias; o0.w = p.y + bias;
            p = unpk(acc[r][2]); o1.x = p.x + bias; o1.y = p.y + bias;
            p = unpk(acc[r][3]); o1.z = p.x + bias; o1.w = p.y + bias;
            *(float4*)(outp + (size_t)row*HWP + t0)     = o0;
            *(float4*)(outp + (size_t)row*HWP + t0 + 4) = o1;
        }
    }
}

// ============ K2: depthwise 3x3, SAME ============
__global__ void __launch_bounds__(192) k2_dw(const float* __restrict__ dww,
                                             const float* __restrict__ dwb)
{
    __shared__ float rows[10][WW];
    int bc = blockIdx.x;            // b*288 + ch
    int ch = bc % C3;
    int y0 = blockIdx.y * 8;
    int xc = threadIdx.x;
    const float* in = g_qkv + (size_t)bc * HWP;
    #pragma unroll
    for (int r = 0; r < 10; r++) {
        int y = y0 - 1 + r;
        rows[r][xc] = (y >= 0 && y < HH) ? in[y*WW + xc] : 0.f;
    }
    __syncthreads();
    float w[9];
    #pragma unroll
    for (int q = 0; q < 9; q++) w[q] = dww[ch*9 + q];
    float bias = dwb[ch];
    float* outp = g_qkvd + (size_t)bc * HWP;
    bool hasL = (xc > 0), hasR = (xc < WW - 1);
    #pragma unroll
    for (int ry = 0; ry < 8; ry++) {
        float acc = bias;
        #pragma unroll
        for (int dy = 0; dy < 3; dy++) {
            const float* rr = rows[ry + dy];
            float m = rr[xc];
            float l = hasL ? rr[xc - 1] : 0.f;
            float r2 = hasR ? rr[xc + 1] : 0.f;
            acc += w[dy*3]*l + w[dy*3+1]*m + w[dy*3+2]*r2;
        }
        outp[(y0 + ry)*WW + xc] = acc;
    }
}

// ============ K3: Gram + sum-of-squares partials ============
__global__ void __launch_bounds__(256) k3_gram()
{
    __shared__ __align__(16) float qs[32*68];
    __shared__ __align__(16) float ks[32*68];
    int bh = blockIdx.x;
    int chunk = blockIdx.y;
    int b = bh / NH, h = bh % NH;
    int tid = threadIdx.x;
    int i  = tid >> 3;
    int j0 = (tid & 7) * 4;
    const float* qbase = g_qkvd + ((size_t)b*C3 + h*HD)*HWP;
    const float* kbase = g_qkvd + ((size_t)b*C3 + 96 + h*HD)*HWP;
    int pstart = chunk * CHUNK;

    u64 acc2[4] = {0,0,0,0};
    u64 aq2 = 0;
    u64 ak2[4] = {0,0,0,0};
    bool doq = ((tid & 7) == 0);
    bool dok = (i == 0);

    for (int ps = 0; ps < CHUNK; ps += 64) {
        for (int idx = tid; idx < 32*64; idx += 256) {
            int ci = idx >> 6, t = idx & 63;
            int p = pstart + ps + t;
            qs[ci*68 + t] = qbase[(size_t)ci*HWP + p];
            ks[ci*68 + t] = kbase[(size_t)ci*HWP + p];
        }
        __syncthreads();
        #pragma unroll 4
        for (int p = 0; p < 64; p += 4) {
            ulonglong2 qv = *(const ulonglong2*)&qs[i*68 + p];
            ulonglong2 k0 = *(const ulonglong2*)&ks[(j0+0)*68 + p];
            ulonglong2 k1 = *(const ulonglong2*)&ks[(j0+1)*68 + p];
            ulonglong2 k2 = *(const ulonglong2*)&ks[(j0+2)*68 + p];
            ulonglong2 k3 = *(const ulonglong2*)&ks[(j0+3)*68 + p];
            fma2(acc2[0], qv.x, k0.x); fma2(acc2[0], qv.y, k0.y);
            fma2(acc2[1], qv.x, k1.x); fma2(acc2[1], qv.y, k1.y);
            fma2(acc2[2], qv.x, k2.x); fma2(acc2[2], qv.y, k2.y);
            fma2(acc2[3], qv.x, k3.x); fma2(acc2[3], qv.y, k3.y);
            if (doq) { fma2(aq2, qv.x, qv.x); fma2(aq2, qv.y, qv.y); }
            if (dok) {
                fma2(ak2[0], k0.x, k0.x); fma2(ak2[0], k0.y, k0.y);
                fma2(ak2[1], k1.x, k1.x); fma2(ak2[1], k1.y, k1.y);
                fma2(ak2[2], k2.x, k2.x); fma2(ak2[2], k2.y, k2.y);
                fma2(ak2[3], k3.x, k3.x); fma2(ak2[3], k3.y, k3.y);
            }
        }
        __syncthreads();
    }
    float* Sp = g_Sp + (((size_t)chunk*BB + b)*NH + h)*HD*HD;
    #pragma unroll
    for (int jj = 0; jj < 4; jj++) {
        float2 v = unpk(acc2[jj]);
        Sp[i*32 + j0 + jj] = v.x + v.y;
    }
    float* sqp = g_sqp + ((size_t)chunk*BB + b)*192;
    if (doq) { float2 v = unpk(aq2); sqp[h*HD + i] = v.x + v.y; }
    if (dok) {
        #pragma unroll
        for (int jj = 0; jj < 4; jj++) {
            float2 v = unpk(ak2[jj]);
            sqp[96 + h*HD + j0 + jj] = v.x + v.y;
        }
    }
}

// ============ K4: normalize + relu + softmax ============
__global__ void k4_attn(const float* __restrict__ temp)
{
    int bh = blockIdx.x;
    int b = bh / NH, h = bh % NH;
    int i = threadIdx.x;  // 0..31
    __shared__ float nk[32];
    float sq = 0.f, sk = 0.f;
    #pragma unroll
    for (int c = 0; c < NCHUNK; c++) {
        const float* sqp = g_sqp + ((size_t)c*BB + b)*192;
        sq += sqp[h*HD + i];
        sk += sqp[96 + h*HD + i];
    }
    float nq = fmaxf(sqrtf(sq), 1e-12f);
    nk[i] = fmaxf(sqrtf(sk), 1e-12f);
    __syncwarp();
    float tp = temp[h];
    float v[32];
    float mx = 0.f;
    #pragma unroll
    for (int j = 0; j < 32; j++) {
        float s = 0.f;
        #pragma unroll
        for (int c = 0; c < NCHUNK; c++)
            s += g_Sp[(((size_t)c*BB + b)*NH + h)*1024 + i*32 + j];
        s = s / (nq * nk[j]) * tp;
        s = fmaxf(s, 0.f);
        v[j] = s;
        mx = fmaxf(mx, s);
    }
    float sum = 0.f;
    #pragma unroll
    for (int j = 0; j < 32; j++) { v[j] = expf(v[j] - mx); sum += v[j]; }
    float inv = 1.f / sum;
    #pragma unroll
    for (int j = 0; j < 32; j++)
        g_A[(size_t)bh*1024 + i*32 + j] = v[j] * inv;
}

// ============ K5: attn@v + proj + residual + LN2 + FFN ============
__global__ void __launch_bounds__(256) k5_fused(
    const float* __restrict__ x,
    const float* __restrict__ ln2w,  const float* __restrict__ ln2b,
    const float* __restrict__ projw, const float* __restrict__ projb,
    const float* __restrict__ c1w,   const float* __restrict__ c1b,
    const float* __restrict__ c2w,   const float* __restrict__ c2b,
    const float* __restrict__ betac, const float* __restrict__ gamma,
    float* __restrict__ out)
{
    __shared__ __align__(16) float bufA[96*ST];  // v -> y/yn (in place)
    __shared__ __align__(16) float bufB[96*ST];  // attn_out -> gated g
    int b  = blockIdx.x / NTILE;
    int p0 = (blockIdx.x % NTILE) * TILE;
    int tid = threadIdx.x;
    int rg = tid >> 3, cg = tid & 7;
    int t0 = cg * 8;

    const float* vbase = g_qkvd + ((size_t)b*C3 + 192)*HWP + p0;
    for (int idx = tid; idx < 96*TILE; idx += 256) {
        int c = idx >> 6, t = idx & 63;
        bufA[c*ST + t] = vbase[(size_t)c*HWP + t];
    }
    __syncthreads();

    // attn_out = A @ v -> bufB (A read from global, L2-resident 12KB/batch)
    #pragma unroll
    for (int r = 0; r < 3; r++) {
        int row = rg*3 + r;
        int h = row >> 5, ii = row & 31;
        const float* arow = g_A + ((size_t)b*NH + h)*1024 + ii*32;
        const float* vrow = bufA + (h*32)*ST + t0;
        u64 a0 = 0, a1 = 0, a2 = 0, a3 = 0;
        #pragma unroll
        for (int j = 0; j < 32; j++) {
            u64 ab = bcast2(arow[j]);
            ulonglong2 v01 = *(const ulonglong2*)(vrow + j*ST);
            ulonglong2 v23 = *(const ulonglong2*)(vrow + j*ST + 4);
            fma2(a0, ab, v01.x); fma2(a1, ab, v01.y);
            fma2(a2, ab, v23.x); fma2(a3, ab, v23.y);
        }
        *(u64*)&bufB[row*ST + t0]     = a0;
        *(u64*)&bufB[row*ST + t0 + 2] = a1;
        *(u64*)&bufB[row*ST + t0 + 4] = a2;
        *(u64*)&bufB[row*ST + t0 + 6] = a3;
    }
    __syncthreads();

    // proj + residual: y = x + (proj(attn_out)+pb)*betac -> bufA + registers
    float yreg[3][8];
    {
        u64 acc[3][4];
        #pragma unroll
        for (int r = 0; r < 3; r++)
            #pragma unroll
            for (int c = 0; c < 4; c++) acc[r][c] = 0ull;
        gemm_3row(projw + (size_t)(rg*3)*96, bufB, t0, acc);
        #pragma unroll
        for (int r = 0; r < 3; r++) {
            int row = rg*3 + r;
            float pb = projb[row], bc = betac[row];
            const float* xrow = x + ((size_t)b*CC + row)*HWP + p0 + t0;
            #pragma unroll
            for (int c4 = 0; c4 < 4; c4++) {
                float2 p = unpk(acc[r][c4]);
                float2 xv = *(const float2*)(xrow + c4*2);
                float y0 = xv.x + (p.x + pb)*bc;
                float y1 = xv.y + (p.y + pb)*bc;
                yreg[r][c4*2]   = y0;
                yreg[r][c4*2+1] = y1;
                bufA[row*ST + t0 + c4*2]     = y0;
                bufA[row*ST + t0 + c4*2 + 1] = y1;
            }
        }
    }
    __syncthreads();

    // LN2 in place: bufA = yn  (thread t owns column t exclusively)
    if (tid < TILE) {
        float s = 0.f, s2 = 0.f;
        #pragma unroll
        for (int c = 0; c < 96; c++) { float v = bufA[c*ST + tid]; s += v; s2 += v*v; }
        float mu  = s * (1.0f/96.0f);
        float var = fmaxf(s2 * (1.0f/96.0f) - mu*mu, 0.f);
        float rs  = rsqrtf(var + 1e-6f);
        #pragma unroll
        for (int c = 0; c < 96; c++) {
            float v = bufA[c*ST + tid];
            bufA[c*ST + tid] = (v - mu) * rs * ln2w[c] + ln2b[c];
        }
    }
    __syncthreads();

    // conv1 f1 -> bufB ; then f2, gate in place (same thread owns same cells)
    {
        u64 acc[3][4];
        #pragma unroll
        for (int r = 0; r < 3; r++)
            #pragma unroll
            for (int c = 0; c < 4; c++) acc[r][c] = 0ull;
        gemm_3row(c1w + (size_t)(rg*3)*96, bufA, t0, acc);
        #pragma unroll
        for (int r = 0; r < 3; r++) {
            int row = rg*3 + r;
            float b1 = c1b[row];
            #pragma unroll
            for (int c4 = 0; c4 < 4; c4++) {
                float2 p = unpk(acc[r][c4]);
                bufB[row*ST + t0 + c4*2]     = p.x + b1;
                bufB[row*ST + t0 + c4*2 + 1] = p.y + b1;
            }
        }
    }
    {
        u64 acc[3][4];
        #pragma unroll
        for (int r = 0; r < 3; r++)
            #pragma unroll
            for (int c = 0; c < 4; c++) acc[r][c] = 0ull;
        gemm_3row(c1w + (size_t)(96 + rg*3)*96, bufA, t0, acc);
        #pragma unroll
        for (int r = 0; r < 3; r++) {
            int row = rg*3 + r;
            float b2 = c1b[96 + row];
            #pragma unroll
            for (int c4 = 0; c4 < 4; c4++) {
                float2 p = unpk(acc[r][c4]);
                bufB[row*ST + t0 + c4*2]     *= (p.x + b2);
                bufB[row*ST + t0 + c4*2 + 1] *= (p.y + b2);
            }
        }
    }
    __syncthreads();

    // conv2 + final residual: out = y + (conv2(g)+cb)*gamma
    {
        u64 acc[3][4];
        #pragma unroll
        for (int r = 0; r < 3; r++)
            #pragma unroll
            for (int c = 0; c < 4; c++) acc[r][c] = 0ull;
        gemm_3row(c2w + (size_t)(rg*3)*96, bufB, t0, acc);
        #pragma unroll
        for (int r = 0; r < 3; r++) {
            int row = rg*3 + r;
            float cb = c2b[row], gm = gamma[row];
            float* orow = out + ((size_t)b*CC + row)*HWP + p0 + t0;
            #pragma unroll
            for (int c4 = 0; c4 < 4; c4++) {
                float2 p = unpk(acc[r][c4]);
                float2 ov;
                ov.x = yreg[r][c4*2]   + (p.x + cb)*gm;
                ov.y = yreg[r][c4*2+1] + (p.y + cb)*gm;
                *(float2*)(orow + c4*2) = ov;
            }
        }
    }
}

extern "C" void kernel_launch(void* const* d_in, const int* in_sizes, int n_in,
                              void* d_out, int out_size) {
    (void)in_sizes; (void)n_in; (void)out_size;
    const float* x      = (const float*)d_in[0];
    const float* ln1_w  = (const float*)d_in[1];
    const float* ln1_b  = (const float*)d_in[2];
    const float* ln2_w  = (const float*)d_in[3];
    const float* ln2_b  = (const float*)d_in[4];
    const float* qkv_w  = (const float*)d_in[5];
    const float* qkv_b  = (const float*)d_in[6];
    const float* dw_w   = (const float*)d_in[7];
    const float* dw_b   = (const float*)d_in[8];
    const float* temp   = (const float*)d_in[9];
    const float* proj_w = (const float*)d_in[10];
    const float* proj_b = (const float*)d_in[11];
    const float* c1_w   = (const float*)d_in[12];
    const float* c1_b   = (const float*)d_in[13];
    const float* c2_w   = (const float*)d_in[14];
    const float* c2_b   = (const float*)d_in[15];
    const float* betac  = (const float*)d_in[16];
    const float* gamma  = (const float*)d_in[17];
    float* out = (float*)d_out;

    k1_ln_qkv<<<BB*NTILE, 256>>>(x, ln1_w, ln1_b, qkv_w, qkv_b);
    k2_dw<<<dim3(BB*C3, HH/8), 192>>>(dw_w, dw_b);
    k3_gram<<<dim3(BB*NH, NCHUNK), 256>>>();
    k4_attn<<<BB*NH, 32>>>(temp);
    k5_fused<<<BB*NTILE, 256>>>(x, ln2_w, ln2_b, proj_w, proj_b,
                                c1_w, c1_b, c2_w, c2_b, betac, gamma, out);
}

// round 3
// speedup vs baseline: 2.1084x; 2.1084x over previous
#include <cuda_runtime.h>

#define BB 8
#define CC 96
#define C3 288
#define HH 192
#define WW 192
#define HWP (HH*WW)
#define NH 3
#define HD 32
#define NCHUNK 16
#define CHUNK (HWP/NCHUNK)
#define PXT 128
#define NPXT (HWP/PXT)      // 288
#define AST 136             // act smem stride (bank-conflict-free for mma B frags)

typedef unsigned long long u64;
typedef unsigned int u32;

// ---------------- scratch ----------------
__device__ float g_qkv [(size_t)BB*C3*HWP];
__device__ float g_qkvd[(size_t)BB*C3*HWP];
__device__ float g_Sp  [NCHUNK*BB*NH*HD*HD];
__device__ float g_sqp [NCHUNK*BB*192];
__device__ float g_A   [BB*NH*HD*HD];
// packed tf32 weights (A-fragment order)
__device__ float g_pk_qkv [288*96];
__device__ float g_pk_proj[96*96];
__device__ float g_pk_c1  [192*96];
__device__ float g_pk_c2  [96*96];

// ---------------- helpers ----------------
__device__ __forceinline__ u64 bcast2(float a) {
    u64 r; asm("mov.b64 %0, {%1, %1};" : "=l"(r) : "f"(a)); return r;
}
__device__ __forceinline__ void fma2(u64& d, u64 a, u64 b) {
    asm("fma.rn.f32x2 %0, %1, %2, %0;" : "+l"(d) : "l"(a), "l"(b));
}
__device__ __forceinline__ float2 unpk(u64 v) {
    float2 r; asm("mov.b64 {%0, %1}, %2;" : "=f"(r.x), "=f"(r.y) : "l"(v)); return r;
}
__device__ __forceinline__ float tf32r(float v) {
    u32 u; asm("cvt.rna.tf32.f32 %0, %1;" : "=r"(u) : "f"(v));
    return __uint_as_float(u);
}
__device__ __forceinline__ void mma8(float d[4], const u32 a[4], u32 b0, u32 b1) {
    asm volatile(
        "mma.sync.aligned.m16n8k8.row.col.f32.tf32.tf32.f32 "
        "{%0,%1,%2,%3},{%4,%5,%6,%7},{%8,%9},{%0,%1,%2,%3};"
        : "+f"(d[0]), "+f"(d[1]), "+f"(d[2]), "+f"(d[3])
        : "r"(a[0]), "r"(a[1]), "r"(a[2]), "r"(a[3]), "r"(b0), "r"(b1));
}
__device__ __forceinline__ void ldA(u32 a[4], const float* pk, int frag, int lane) {
    float4 f = *(const float4*)(pk + (size_t)frag*128 + lane*4);
    a[0] = __float_as_uint(f.x); a[1] = __float_as_uint(f.y);
    a[2] = __float_as_uint(f.z); a[3] = __float_as_uint(f.w);
}

// ============ K0: pack weights into tf32 A-fragment order ============
__global__ void k0_pack(const float* __restrict__ qkvw, const float* __restrict__ projw,
                        const float* __restrict__ c1w,  const float* __restrict__ c2w)
{
    int e = blockIdx.x*256 + threadIdx.x;
    const float* src; float* dst; int idx = e;
    if      (idx < 27648) { src = qkvw; dst = g_pk_qkv; }
    else if (idx < 36864) { idx -= 27648; src = projw; dst = g_pk_proj; }
    else if (idx < 55296) { idx -= 36864; src = c1w;  dst = g_pk_c1; }
    else if (idx < 64512) { idx -= 55296; src = c2w;  dst = g_pk_c2; }
    else return;
    int f = idx >> 7, L = (idx >> 2) & 31, r = idx & 3;
    int mt = f / 12, ks = f % 12;
    int row = mt*16 + (L >> 2) + (r & 1)*8;
    int col = ks*8 + (L & 3) + ((r >> 1) & 1)*4;
    dst[idx] = tf32r(src[row*96 + col]);
}

// ============ K1: LN1 + qkv (tensor cores) ============
__global__ void __launch_bounds__(256) k1_ln_qkv(
    const float* __restrict__ x,    const float* __restrict__ ln1w,
    const float* __restrict__ ln1b, const float* __restrict__ qkvb)
{
    extern __shared__ __align__(16) float xs[];   // 96 * AST
    int b  = blockIdx.x / NPXT;
    int p0 = (blockIdx.x % NPXT) * PXT;
    int tid = threadIdx.x;

    const float* xb = x + (size_t)b*CC*HWP + p0;
    for (int idx = tid; idx < 96*PXT; idx += 256) {
        int c = idx >> 7, t = idx & 127;
        xs[c*AST + t] = xb[(size_t)c*HWP + t];
    }
    __syncthreads();
    if (tid < PXT) {
        float s = 0.f, s2 = 0.f;
        #pragma unroll
        for (int c = 0; c < 96; c++) { float v = xs[c*AST + tid]; s += v; s2 += v*v; }
        float mu  = s * (1.0f/96.0f);
        float var = fmaxf(s2 * (1.0f/96.0f) - mu*mu, 0.f);
        float rs  = rsqrtf(var + 1e-6f);
        #pragma unroll
        for (int c = 0; c < 96; c++) {
            float v = xs[c*AST + tid];
            xs[c*AST + tid] = tf32r((v - mu) * rs * ln1w[c] + ln1b[c]);
        }
    }
    __syncthreads();

    int w = tid >> 5, lane = tid & 31;
    int g = lane >> 2, tig = lane & 3;
    int pxw = w * 16;
    #pragma unroll 1
    for (int mtp = 0; mtp < 9; mtp++) {
        float D[2][2][4];
        #pragma unroll
        for (int m = 0; m < 2; m++)
            #pragma unroll
            for (int n = 0; n < 2; n++)
                #pragma unroll
                for (int c = 0; c < 4; c++) D[m][n][c] = 0.f;
        #pragma unroll 2
        for (int ks = 0; ks < 12; ks++) {
            u32 A0[4], A1[4];
            ldA(A0, g_pk_qkv, (2*mtp)*12 + ks, lane);
            ldA(A1, g_pk_qkv, (2*mtp + 1)*12 + ks, lane);
            u32 b00 = __float_as_uint(xs[(ks*8 + tig)*AST + pxw + g]);
            u32 b01 = __float_as_uint(xs[(ks*8 + tig + 4)*AST + pxw + g]);
            u32 b10 = __float_as_uint(xs[(ks*8 + tig)*AST + pxw + 8 + g]);
            u32 b11 = __float_as_uint(xs[(ks*8 + tig + 4)*AST + pxw + 8 + g]);
            mma8(D[0][0], A0, b00, b01); mma8(D[0][1], A0, b10, b11);
            mma8(D[1][0], A1, b00, b01); mma8(D[1][1], A1, b10, b11);
        }
        #pragma unroll
        for (int m = 0; m < 2; m++) {
            int r0 = (2*mtp + m)*16 + g;
            float bz0 = qkvb[r0], bz1 = qkvb[r0 + 8];
            #pragma unroll
            for (int n = 0; n < 2; n++) {
                int c0 = p0 + pxw + n*8 + 2*tig;
                *(float2*)(g_qkv + ((size_t)b*C3 + r0)*HWP + c0) =
                    make_float2(D[m][n][0] + bz0, D[m][n][1] + bz0);
                *(float2*)(g_qkv + ((size_t)b*C3 + r0 + 8)*HWP + c0) =
                    make_float2(D[m][n][2] + bz1, D[m][n][3] + bz1);
            }
        }
    }
}

// ============ K2: depthwise 3x3, SAME ============
__global__ void __launch_bounds__(192) k2_dw(const float* __restrict__ dww,
                                             const float* __restrict__ dwb)
{
    __shared__ float rows[10][WW];
    int bc = blockIdx.x;
    int ch = bc % C3;
    int y0 = blockIdx.y * 8;
    int xc = threadIdx.x;
    const float* in = g_qkv + (size_t)bc * HWP;
    #pragma unroll
    for (int r = 0; r < 10; r++) {
        int y = y0 - 1 + r;
        rows[r][xc] = (y >= 0 && y < HH) ? in[y*WW + xc] : 0.f;
    }
    __syncthreads();
    float w[9];
    #pragma unroll
    for (int q = 0; q < 9; q++) w[q] = dww[ch*9 + q];
    float bias = dwb[ch];
    float* outp = g_qkvd + (size_t)bc * HWP;
    bool hasL = (xc > 0), hasR = (xc < WW - 1);
    #pragma unroll
    for (int ry = 0; ry < 8; ry++) {
        float acc = bias;
        #pragma unroll
        for (int dy = 0; dy < 3; dy++) {
            const float* rr = rows[ry + dy];
            float m = rr[xc];
            float l = hasL ? rr[xc - 1] : 0.f;
            float r2 = hasR ? rr[xc + 1] : 0.f;
            acc += w[dy*3]*l + w[dy*3+1]*m + w[dy*3+2]*r2;
        }
        outp[(y0 + ry)*WW + xc] = acc;
    }
}

// ============ K3: Gram + sumsq partials (fp32) ============
__global__ void __launch_bounds__(256) k3_gram()
{
    __shared__ __align__(16) float qs[32*68];
    __shared__ __align__(16) float ks[32*68];
    int bh = blockIdx.x;
    int chunk = blockIdx.y;
    int b = bh / NH, h = bh % NH;
    int tid = threadIdx.x;
    int i  = tid >> 3;
    int j0 = (tid & 7) * 4;
    const float* qbase = g_qkvd + ((size_t)b*C3 + h*HD)*HWP;
    const float* kbase = g_qkvd + ((size_t)b*C3 + 96 + h*HD)*HWP;
    int pstart = chunk * CHUNK;

    u64 acc2[4] = {0,0,0,0};
    u64 aq2 = 0;
    u64 ak2[4] = {0,0,0,0};
    bool doq = ((tid & 7) == 0);
    bool dok = (i == 0);

    for (int ps = 0; ps < CHUNK; ps += 64) {
        for (int idx = tid; idx < 32*64; idx += 256) {
            int ci = idx >> 6, t = idx & 63;
            int p = pstart + ps + t;
            qs[ci*68 + t] = qbase[(size_t)ci*HWP + p];
            ks[ci*68 + t] = kbase[(size_t)ci*HWP + p];
        }
        __syncthreads();
        #pragma unroll 4
        for (int p = 0; p < 64; p += 4) {
            ulonglong2 qv = *(const ulonglong2*)&qs[i*68 + p];
            ulonglong2 k0 = *(const ulonglong2*)&ks[(j0+0)*68 + p];
            ulonglong2 k1 = *(const ulonglong2*)&ks[(j0+1)*68 + p];
            ulonglong2 k2 = *(const ulonglong2*)&ks[(j0+2)*68 + p];
            ulonglong2 k3 = *(const ulonglong2*)&ks[(j0+3)*68 + p];
            fma2(acc2[0], qv.x, k0.x); fma2(acc2[0], qv.y, k0.y);
            fma2(acc2[1], qv.x, k1.x); fma2(acc2[1], qv.y, k1.y);
            fma2(acc2[2], qv.x, k2.x); fma2(acc2[2], qv.y, k2.y);
            fma2(acc2[3], qv.x, k3.x); fma2(acc2[3], qv.y, k3.y);
            if (doq) { fma2(aq2, qv.x, qv.x); fma2(aq2, qv.y, qv.y); }
            if (dok) {
                fma2(ak2[0], k0.x, k0.x); fma2(ak2[0], k0.y, k0.y);
                fma2(ak2[1], k1.x, k1.x); fma2(ak2[1], k1.y, k1.y);
                fma2(ak2[2], k2.x, k2.x); fma2(ak2[2], k2.y, k2.y);
                fma2(ak2[3], k3.x, k3.x); fma2(ak2[3], k3.y, k3.y);
            }
        }
        __syncthreads();
    }
    float* Sp = g_Sp + (((size_t)chunk*BB + b)*NH + h)*HD*HD;
    #pragma unroll
    for (int jj = 0; jj < 4; jj++) {
        float2 v = unpk(acc2[jj]);
        Sp[i*32 + j0 + jj] = v.x + v.y;
    }
    float* sqp = g_sqp + ((size_t)chunk*BB + b)*192;
    if (doq) { float2 v = unpk(aq2); sqp[h*HD + i] = v.x + v.y; }
    if (dok) {
        #pragma unroll
        for (int jj = 0; jj < 4; jj++) {
            float2 v = unpk(ak2[jj]);
            sqp[96 + h*HD + j0 + jj] = v.x + v.y;
        }
    }
}

// ============ K4: normalize + relu + softmax (emits tf32-rounded A) ============
__global__ void k4_attn(const float* __restrict__ temp)
{
    int bh = blockIdx.x;
    int b = bh / NH, h = bh % NH;
    int i = threadIdx.x;
    __shared__ float nk[32];
    float sq = 0.f, sk = 0.f;
    #pragma unroll
    for (int c = 0; c < NCHUNK; c++) {
        const float* sqp = g_sqp + ((size_t)c*BB + b)*192;
        sq += sqp[h*HD + i];
        sk += sqp[96 + h*HD + i];
    }
    float nq = fmaxf(sqrtf(sq), 1e-12f);
    nk[i] = fmaxf(sqrtf(sk), 1e-12f);
    __syncwarp();
    float tp = temp[h];
    float v[32];
    float mx = 0.f;
    #pragma unroll
    for (int j = 0; j < 32; j++) {
        float s = 0.f;
        #pragma unroll
        for (int c = 0; c < NCHUNK; c++)
            s += g_Sp[(((size_t)c*BB + b)*NH + h)*1024 + i*32 + j];
        s = s / (nq * nk[j]) * tp;
        s = fmaxf(s, 0.f);
        v[j] = s;
        mx = fmaxf(mx, s);
    }
    float sum = 0.f;
    #pragma unroll
    for (int j = 0; j < 32; j++) { v[j] = expf(v[j] - mx); sum += v[j]; }
    float inv = 1.f / sum;
    #pragma unroll
    for (int j = 0; j < 32; j++)
        g_A[(size_t)bh*1024 + i*32 + j] = tf32r(v[j] * inv);
}

// ============ K5: attn@v + proj + residual + LN2 + FFN (tensor cores) ============
__global__ void __launch_bounds__(256) k5_fused(
    const float* __restrict__ x,
    const float* __restrict__ ln2w,  const float* __restrict__ ln2b,
    const float* __restrict__ projb,
    const float* __restrict__ c1b,   const float* __restrict__ c2b,
    const float* __restrict__ betac, const float* __restrict__ gamma,
    float* __restrict__ out)
{
    extern __shared__ __align__(16) float sm[];
    float* bufA = sm;               // 96*AST : v -> y -> gated g
    float* bufB = sm + 96*AST;      // 96*AST : attn_out -> yn
    int b  = blockIdx.x / NPXT;
    int p0 = (blockIdx.x % NPXT) * PXT;
    int tid = threadIdx.x;
    int w = tid >> 5, lane = tid & 31;
    int g = lane >> 2, tig = lane & 3;
    int pxw = w * 16;

    // stage 0: v tile -> bufA (tf32)
    const float* vbase = g_qkvd + ((size_t)b*C3 + 192)*HWP + p0;
    for (int idx = tid; idx < 96*PXT; idx += 256) {
        int c = idx >> 7, t = idx & 127;
        bufA[c*AST + t] = tf32r(vbase[(size_t)c*HWP + t]);
    }
    __syncthreads();

    // stage 1: attn_out = A @ v -> bufB (tf32)
    #pragma unroll 1
    for (int h = 0; h < NH; h++) {
        const float* Ab = g_A + ((size_t)b*NH + h)*1024;
        float D[2][2][4];
        #pragma unroll
        for (int m = 0; m < 2; m++)
            #pragma unroll
            for (int n = 0; n < 2; n++)
                #pragma unroll
                for (int c = 0; c < 4; c++) D[m][n][c] = 0.f;
        #pragma unroll
        for (int ksi = 0; ksi < 4; ksi++) {
            u32 b00 = __float_as_uint(bufA[(32*h + ksi*8 + tig)*AST + pxw + g]);
            u32 b01 = __float_as_uint(bufA[(32*h + ksi*8 + tig + 4)*AST + pxw + g]);
            u32 b10 = __float_as_uint(bufA[(32*h + ksi*8 + tig)*AST + pxw + 8 + g]);
            u32 b11 = __float_as_uint(bufA[(32*h + ksi*8 + tig + 4)*AST + pxw + 8 + g]);
            #pragma unroll
            for (int m = 0; m < 2; m++) {
                u32 a[4];
                int i0 = m*16 + g, j0 = ksi*8 + tig;
                a[0] = __float_as_uint(Ab[i0*32 + j0]);
                a[1] = __float_as_uint(Ab[(i0 + 8)*32 + j0]);
                a[2] = __float_as_uint(Ab[i0*32 + j0 + 4]);
                a[3] = __float_as_uint(Ab[(i0 + 8)*32 + j0 + 4]);
                mma8(D[m][0], a, b00, b01);
                mma8(D[m][1], a, b10, b11);
            }
        }
        #pragma unroll
        for (int m = 0; m < 2; m++) {
            int r0 = 32*h + m*16 + g;
            #pragma unroll
            for (int n = 0; n < 2; n++) {
                int cl = pxw + n*8 + 2*tig;
                bufB[r0*AST + cl]       = tf32r(D[m][n][0]);
                bufB[r0*AST + cl + 1]   = tf32r(D[m][n][1]);
                bufB[(r0+8)*AST + cl]   = tf32r(D[m][n][2]);
                bufB[(r0+8)*AST + cl+1] = tf32r(D[m][n][3]);
            }
        }
    }
    __syncthreads();

    // stage 2: y = x + (proj(attn_out)+pb)*betac -> bufA (fp32) + yreg
    float yreg[48];
    #pragma unroll 1
    for (int mtp = 0; mtp < 3; mtp++) {
        float D[2][2][4];
        #pragma unroll
        for (int m = 0; m < 2; m++)
            #pragma unroll
            for (int n = 0; n < 2; n++)
                #pragma unroll
                for (int c = 0; c < 4; c++) D[m][n][c] = 0.f;
        #pragma unroll 2
        for (int ksi = 0; ksi < 12; ksi++) {
            u32 A0[4], A1[4];
            ldA(A0, g_pk_proj, (2*mtp)*12 + ksi, lane);
            ldA(A1, g_pk_proj, (2*mtp + 1)*12 + ksi, lane);
            u32 b00 = __float_as_uint(bufB[(ksi*8 + tig)*AST + pxw + g]);
            u32 b01 = __float_as_uint(bufB[(ksi*8 + tig + 4)*AST + pxw + g]);
            u32 b10 = __float_as_uint(bufB[(ksi*8 + tig)*AST + pxw + 8 + g]);
            u32 b11 = __float_as_uint(bufB[(ksi*8 + tig + 4)*AST + pxw + 8 + g]);
            mma8(D[0][0], A0, b00, b01); mma8(D[0][1], A0, b10, b11);
            mma8(D[1][0], A1, b00, b01); mma8(D[1][1], A1, b10, b11);
        }
        #pragma unroll
        for (int m = 0; m < 2; m++) {
            int r0 = (2*mtp + m)*16 + g;
            float pb0 = projb[r0], bc0 = betac[r0];
            float pb1 = projb[r0 + 8], bc1 = betac[r0 + 8];
            #pragma unroll
            for (int n = 0; n < 2; n++) {
                int cl = pxw + n*8 + 2*tig;
                float2 xv0 = *(const float2*)(x + ((size_t)b*CC + r0)*HWP + p0 + cl);
                float2 xv1 = *(const float2*)(x + ((size_t)b*CC + r0 + 8)*HWP + p0 + cl);
                float y0 = xv0.x + (D[m][n][0] + pb0)*bc0;
                float y1 = xv0.y + (D[m][n][1] + pb0)*bc0;
                float y2 = xv1.x + (D[m][n][2] + pb1)*bc1;
                float y3 = xv1.y + (D[m][n][3] + pb1)*bc1;
                int yi = ((mtp*2 + m)*2 + n)*4;
                yreg[yi] = y0; yreg[yi+1] = y1; yreg[yi+2] = y2; yreg[yi+3] = y3;
                bufA[r0*AST + cl] = y0;       bufA[r0*AST + cl + 1] = y1;
                bufA[(r0+8)*AST + cl] = y2;   bufA[(r0+8)*AST + cl + 1] = y3;
            }
        }
    }
    __syncthreads();

    // stage 3: LN2(bufA) -> bufB (tf32)
    if (tid < PXT) {
        float s = 0.f, s2 = 0.f;
        #pragma unroll
        for (int c = 0; c < 96; c++) { float v = bufA[c*AST + tid]; s += v; s2 += v*v; }
        float mu  = s * (1.0f/96.0f);
        float var = fmaxf(s2 * (1.0f/96.0f) - mu*mu, 0.f);
        float rs  = rsqrtf(var + 1e-6f);
        #pragma unroll
        for (int c = 0; c < 96; c++) {
            float v = bufA[c*AST + tid];
            bufB[c*AST + tid] = tf32r((v - mu) * rs * ln2w[c] + ln2b[c]);
        }
    }
    __syncthreads();

    // stage 4: g = (conv1a(yn)+b1)*(conv1b(yn)+b2) -> bufA (tf32)
    #pragma unroll 1
    for (int mtp = 0; mtp < 3; mtp++) {
        float D1[2][2][4], D2[2][2][4];
        #pragma unroll
        for (int m = 0; m < 2; m++)
            #pragma unroll
            for (int n = 0; n < 2; n++)
                #pragma unroll
                for (int c = 0; c < 4; c++) { D1[m][n][c] = 0.f; D2[m][n][c] = 0.f; }
        #pragma unroll 1
        for (int ksi = 0; ksi < 12; ksi++) {
            u32 A0[4], A1[4], A2[4], A3[4];
            ldA(A0, g_pk_c1, (2*mtp)*12 + ksi, lane);
            ldA(A1, g_pk_c1, (2*mtp + 1)*12 + ksi, lane);
            ldA(A2, g_pk_c1, (2*mtp + 6)*12 + ksi, lane);
            ldA(A3, g_pk_c1, (2*mtp + 7)*12 + ksi, lane);
            u32 b00 = __float_as_uint(bufB[(ksi*8 + tig)*AST + pxw + g]);
            u32 b01 = __float_as_uint(bufB[(ksi*8 + tig + 4)*AST + pxw + g]);
            u32 b10 = __float_as_uint(bufB[(ksi*8 + tig)*AST + pxw + 8 + g]);
            u32 b11 = __float_as_uint(bufB[(ksi*8 + tig + 4)*AST + pxw + 8 + g]);
            mma8(D1[0][0], A0, b00, b01); mma8(D1[0][1], A0, b10, b11);
            mma8(D1[1][0], A1, b00, b01); mma8(D1[1][1], A1, b10, b11);
            mma8(D2[0][0], A2, b00, b01); mma8(D2[0][1], A2, b10, b11);
            mma8(D2[1][0], A3, b00, b01); mma8(D2[1][1], A3, b10, b11);
        }
        #pragma unroll
        for (int m = 0; m < 2; m++) {
            int r0 = (2*mtp + m)*16 + g;
            float ba0 = c1b[r0], bb0 = c1b[96 + r0];
            float ba1 = c1b[r0 + 8], bb1 = c1b[96 + r0 + 8];
            #pragma unroll
            for (int n = 0; n < 2; n++) {
                int cl = pxw + n*8 + 2*tig;
                bufA[r0*AST + cl]       = tf32r((D1[m][n][0] + ba0)*(D2[m][n][0] + bb0));
                bufA[r0*AST + cl + 1]   = tf32r((D1[m][n][1] + ba0)*(D2[m][n][1] + bb0));
                bufA[(r0+8)*AST + cl]   = tf32r((D1[m][n][2] + ba1)*(D2[m][n][2] + bb1));
                bufA[(r0+8)*AST + cl+1] = tf32r((D1[m][n][3] + ba1)*(D2[m][n][3] + bb1));
            }
        }
    }
    __syncthreads();

    // stage 5: out = y + (conv2(g)+cb)*gamma
    #pragma unroll 1
    for (int mtp = 0; mtp < 3; mtp++) {
        float D[2][2][4];
        #pragma unroll
        for (int m = 0; m < 2; m++)
            #pragma unroll
            for (int n = 0; n < 2; n++)
                #pragma unroll
                for (int c = 0; c < 4; c++) D[m][n][c] = 0.f;
        #pragma unroll 2
        for (int ksi = 0; ksi < 12; ksi++) {
            u32 A0[4], A1[4];
            ldA(A0, g_pk_c2, (2*mtp)*12 + ksi, lane);
            ldA(A1, g_pk_c2, (2*mtp + 1)*12 + ksi, lane);
            u32 b00 = __float_as_uint(bufA[(ksi*8 + tig)*AST + pxw + g]);
            u32 b01 = __float_as_uint(bufA[(ksi*8 + tig + 4)*AST + pxw + g]);
            u32 b10 = __float_as_uint(bufA[(ksi*8 + tig)*AST + pxw + 8 + g]);
            u32 b11 = __float_as_uint(bufA[(ksi*8 + tig + 4)*AST + pxw + 8 + g]);
            mma8(D[0][0], A0, b00, b01); mma8(D[0][1], A0, b10, b11);
            mma8(D[1][0], A1, b00, b01); mma8(D[1][1], A1, b10, b11);
        }
        #pragma unroll
        for (int m = 0; m < 2; m++) {
            int r0 = (2*mtp + m)*16 + g;
            float cb0 = c2b[r0], gm0 = gamma[r0];
            float cb1 = c2b[r0 + 8], gm1 = gamma[r0 + 8];
            #pragma unroll
            for (int n = 0; n < 2; n++) {
                int cl = pxw + n*8 + 2*tig;
                int yi = ((mtp*2 + m)*2 + n)*4;
                float2 o0, o1;
                o0.x = yreg[yi]   + (D[m][n][0] + cb0)*gm0;
                o0.y = yreg[yi+1] + (D[m][n][1] + cb0)*gm0;
                o1.x = yreg[yi+2] + (D[m][n][2] + cb1)*gm1;
                o1.y = yreg[yi+3] + (D[m][n][3] + cb1)*gm1;
                *(float2*)(out + ((size_t)b*CC + r0)*HWP + p0 + cl) = o0;
                *(float2*)(out + ((size_t)b*CC + r0 + 8)*HWP + p0 + cl) = o1;
            }
        }
    }
}

extern "C" void kernel_launch(void* const* d_in, const int* in_sizes, int n_in,
                              void* d_out, int out_size) {
    (void)in_sizes; (void)n_in; (void)out_size;
    const float* x      = (const float*)d_in[0];
    const float* ln1_w  = (const float*)d_in[1];
    const float* ln1_b  = (const float*)d_in[2];
    const float* ln2_w  = (const float*)d_in[3];
    const float* ln2_b  = (const float*)d_in[4];
    const float* qkv_w  = (const float*)d_in[5];
    const float* qkv_b  = (const float*)d_in[6];
    const float* dw_w   = (const float*)d_in[7];
    const float* dw_b   = (const float*)d_in[8];
    const float* temp   = (const float*)d_in[9];
    const float* proj_w = (const float*)d_in[10];
    const float* proj_b = (const float*)d_in[11];
    const float* c1_w   = (const float*)d_in[12];
    const float* c1_b   = (const float*)d_in[13];
    const float* c2_w   = (const float*)d_in[14];
    const float* c2_b   = (const float*)d_in[15];
    const float* betac  = (const float*)d_in[16];
    const float* gamma  = (const float*)d_in[17];
    float* out = (float*)d_out;

    cudaFuncSetAttribute(k1_ln_qkv, cudaFuncAttributeMaxDynamicSharedMemorySize, 96*AST*4);
    cudaFuncSetAttribute(k5_fused,  cudaFuncAttributeMaxDynamicSharedMemorySize, 2*96*AST*4);

    k0_pack<<<252, 256>>>(qkv_w, proj_w, c1_w, c2_w);
    k1_ln_qkv<<<BB*NPXT, 256, 96*AST*4>>>(x, ln1_w, ln1_b, qkv_b);
    k2_dw<<<dim3(BB*C3, HH/8), 192>>>(dw_w, dw_b);
    k3_gram<<<dim3(BB*NH, NCHUNK), 256>>>();
    k4_attn<<<BB*NH, 32>>>(temp);
    k5_fused<<<BB*NPXT, 256, 2*96*AST*4>>>(x, ln2_w, ln2_b, proj_b,
                                           c1_b, c2_b, betac, gamma, out);
}

// round 4
// speedup vs baseline: 3.1219x; 1.4807x over previous
#include <cuda_runtime.h>

#define BB 8
#define CC 96
#define C3 288
#define HH 192
#define WW 192
#define HWP (HH*WW)
#define NH 3
#define HD 32
#define NCHUNK 16
#define CHUNK (HWP/NCHUNK)
#define PXT 128
#define NPXT (HWP/PXT)      // 288
#define AST 136             // act smem stride for k1/k5
#define GST 132             // gram smem stride

typedef unsigned long long u64;
typedef unsigned int u32;

// ---------------- scratch ----------------
__device__ float g_qkv [(size_t)BB*C3*HWP];
__device__ float g_qkvd[(size_t)BB*C3*HWP];
__device__ float g_Sp  [NCHUNK*BB*NH*HD*HD];
__device__ float g_sqp [NCHUNK*BB*192];
__device__ float g_A   [BB*NH*HD*HD];
// packed tf32 weights (A-fragment order)
__device__ float g_pk_qkv [288*96];
__device__ float g_pk_proj[96*96];
__device__ float g_pk_c1  [192*96];
__device__ float g_pk_c2  [96*96];

// ---------------- helpers ----------------
__device__ __forceinline__ float tf32r(float v) {
    u32 u; asm("cvt.rna.tf32.f32 %0, %1;" : "=r"(u) : "f"(v));
    return __uint_as_float(u);
}
__device__ __forceinline__ void mma8(float d[4], const u32 a[4], u32 b0, u32 b1) {
    asm volatile(
        "mma.sync.aligned.m16n8k8.row.col.f32.tf32.tf32.f32 "
        "{%0,%1,%2,%3},{%4,%5,%6,%7},{%8,%9},{%0,%1,%2,%3};"
        : "+f"(d[0]), "+f"(d[1]), "+f"(d[2]), "+f"(d[3])
        : "r"(a[0]), "r"(a[1]), "r"(a[2]), "r"(a[3]), "r"(b0), "r"(b1));
}
__device__ __forceinline__ void ldA(u32 a[4], const float* pk, int frag, int lane) {
    float4 f = *(const float4*)(pk + (size_t)frag*128 + lane*4);
    a[0] = __float_as_uint(f.x); a[1] = __float_as_uint(f.y);
    a[2] = __float_as_uint(f.z); a[3] = __float_as_uint(f.w);
}

// ============ K0: pack weights into tf32 A-fragment order ============
__global__ void k0_pack(const float* __restrict__ qkvw, const float* __restrict__ projw,
                        const float* __restrict__ c1w,  const float* __restrict__ c2w)
{
    int e = blockIdx.x*256 + threadIdx.x;
    const float* src; float* dst; int idx = e;
    if      (idx < 27648) { src = qkvw; dst = g_pk_qkv; }
    else if (idx < 36864) { idx -= 27648; src = projw; dst = g_pk_proj; }
    else if (idx < 55296) { idx -= 36864; src = c1w;  dst = g_pk_c1; }
    else if (idx < 64512) { idx -= 55296; src = c2w;  dst = g_pk_c2; }
    else return;
    int f = idx >> 7, L = (idx >> 2) & 31, r = idx & 3;
    int mt = f / 12, ks = f % 12;
    int row = mt*16 + (L >> 2) + (r & 1)*8;
    int col = ks*8 + (L & 3) + ((r >> 1) & 1)*4;
    dst[idx] = tf32r(src[row*96 + col]);
}

// ============ K1: LN1 + qkv (tensor cores) ============
__global__ void __launch_bounds__(256) k1_ln_qkv(
    const float* __restrict__ x,    const float* __restrict__ ln1w,
    const float* __restrict__ ln1b, const float* __restrict__ qkvb)
{
    extern __shared__ __align__(16) float xs[];   // 96 * AST
    int b  = blockIdx.x / NPXT;
    int p0 = (blockIdx.x % NPXT) * PXT;
    int tid = threadIdx.x;

    const float* xb = x + (size_t)b*CC*HWP + p0;
    for (int idx = tid; idx < 96*PXT; idx += 256) {
        int c = idx >> 7, t = idx & 127;
        xs[c*AST + t] = xb[(size_t)c*HWP + t];
    }
    __syncthreads();
    if (tid < PXT) {
        float s = 0.f, s2 = 0.f;
        #pragma unroll
        for (int c = 0; c < 96; c++) { float v = xs[c*AST + tid]; s += v; s2 += v*v; }
        float mu  = s * (1.0f/96.0f);
        float var = fmaxf(s2 * (1.0f/96.0f) - mu*mu, 0.f);
        float rs  = rsqrtf(var + 1e-6f);
        #pragma unroll
        for (int c = 0; c < 96; c++) {
            float v = xs[c*AST + tid];
            xs[c*AST + tid] = tf32r((v - mu) * rs * ln1w[c] + ln1b[c]);
        }
    }
    __syncthreads();

    int w = tid >> 5, lane = tid & 31;
    int g = lane >> 2, tig = lane & 3;
    int pxw = w * 16;
    #pragma unroll 1
    for (int mtp = 0; mtp < 9; mtp++) {
        float D[2][2][4];
        #pragma unroll
        for (int m = 0; m < 2; m++)
            #pragma unroll
            for (int n = 0; n < 2; n++)
                #pragma unroll
                for (int c = 0; c < 4; c++) D[m][n][c] = 0.f;
        #pragma unroll 2
        for (int ks = 0; ks < 12; ks++) {
            u32 A0[4], A1[4];
            ldA(A0, g_pk_qkv, (2*mtp)*12 + ks, lane);
            ldA(A1, g_pk_qkv, (2*mtp + 1)*12 + ks, lane);
            u32 b00 = __float_as_uint(xs[(ks*8 + tig)*AST + pxw + g]);
            u32 b01 = __float_as_uint(xs[(ks*8 + tig + 4)*AST + pxw + g]);
            u32 b10 = __float_as_uint(xs[(ks*8 + tig)*AST + pxw + 8 + g]);
            u32 b11 = __float_as_uint(xs[(ks*8 + tig + 4)*AST + pxw + 8 + g]);
            mma8(D[0][0], A0, b00, b01); mma8(D[0][1], A0, b10, b11);
            mma8(D[1][0], A1, b00, b01); mma8(D[1][1], A1, b10, b11);
        }
        #pragma unroll
        for (int m = 0; m < 2; m++) {
            int r0 = (2*mtp + m)*16 + g;
            float bz0 = qkvb[r0], bz1 = qkvb[r0 + 8];
            #pragma unroll
            for (int n = 0; n < 2; n++) {
                int c0 = p0 + pxw + n*8 + 2*tig;
                *(float2*)(g_qkv + ((size_t)b*C3 + r0)*HWP + c0) =
                    make_float2(D[m][n][0] + bz0, D[m][n][1] + bz0);
                *(float2*)(g_qkv + ((size_t)b*C3 + r0 + 8)*HWP + c0) =
                    make_float2(D[m][n][2] + bz1, D[m][n][3] + bz1);
            }
        }
    }
}

// ============ K2: depthwise 3x3, SAME ============
__global__ void __launch_bounds__(192) k2_dw(const float* __restrict__ dww,
                                             const float* __restrict__ dwb)
{
    __shared__ float rows[10][WW];
    int bc = blockIdx.x;
    int ch = bc % C3;
    int y0 = blockIdx.y * 8;
    int xc = threadIdx.x;
    const float* in = g_qkv + (size_t)bc * HWP;
    #pragma unroll
    for (int r = 0; r < 10; r++) {
        int y = y0 - 1 + r;
        rows[r][xc] = (y >= 0 && y < HH) ? in[y*WW + xc] : 0.f;
    }
    __syncthreads();
    float w[9];
    #pragma unroll
    for (int q = 0; q < 9; q++) w[q] = dww[ch*9 + q];
    float bias = dwb[ch];
    float* outp = g_qkvd + (size_t)bc * HWP;
    bool hasL = (xc > 0), hasR = (xc < WW - 1);
    #pragma unroll
    for (int ry = 0; ry < 8; ry++) {
        float acc = bias;
        #pragma unroll
        for (int dy = 0; dy < 3; dy++) {
            const float* rr = rows[ry + dy];
            float m = rr[xc];
            float l = hasL ? rr[xc - 1] : 0.f;
            float r2 = hasR ? rr[xc + 1] : 0.f;
            acc += w[dy*3]*l + w[dy*3+1]*m + w[dy*3+2]*r2;
        }
        outp[(y0 + ry)*WW + xc] = acc;
    }
}

// ============ K3: Gram + sumsq on tensor cores ============
__global__ void __launch_bounds__(256) k3_gram()
{
    __shared__ __align__(16) float sm[2*32*GST];   // qs | ks ; reused for S reduction
    __shared__ float ssq[8][32];
    float* qs = sm;
    float* ks = sm + 32*GST;
    int bh = blockIdx.x, chunk = blockIdx.y;
    int b = bh / NH, h = bh % NH;
    int tid = threadIdx.x;
    int w = tid >> 5, lane = tid & 31;
    int g = lane >> 2, tig = lane & 3;
    const float* qbase = g_qkvd + ((size_t)b*C3 + h*HD)*HWP + chunk*CHUNK;
    const float* kbase = g_qkvd + ((size_t)b*C3 + 96 + h*HD)*HWP + chunk*CHUNK;

    float D[2][4][4];
    #pragma unroll
    for (int m = 0; m < 2; m++)
        #pragma unroll
        for (int n = 0; n < 4; n++)
            #pragma unroll
            for (int c = 0; c < 4; c++) D[m][n][c] = 0.f;
    float acc = 0.f;
    const float* sq_src = (w < 4) ? qs : ks;
    int pxq = (w & 3) * 32;

    #pragma unroll 1
    for (int st = 0; st < CHUNK/128; st++) {
        int poff = st * 128;
        // stage 128 px of q and k, tf32-rounded
        #pragma unroll
        for (int it = 0; it < 4; it++) {
            int idx = tid + it*256;                  // 0..1023
            int ci = idx >> 5, p4 = (idx & 31) * 4;
            float4 qv = *(const float4*)(qbase + (size_t)ci*HWP + poff + p4);
            float4 kv = *(const float4*)(kbase + (size_t)ci*HWP + poff + p4);
            qv.x = tf32r(qv.x); qv.y = tf32r(qv.y); qv.z = tf32r(qv.z); qv.w = tf32r(qv.w);
            kv.x = tf32r(kv.x); kv.y = tf32r(kv.y); kv.z = tf32r(kv.z); kv.w = tf32r(kv.w);
            *(float4*)(qs + ci*GST + p4) = qv;
            *(float4*)(ks + ci*GST + p4) = kv;
        }
        __syncthreads();

        // each warp: 16-px K-slice, full 32x32 tile (2 m-tiles x 4 n-tiles)
        #pragma unroll
        for (int kstep = 0; kstep < 2; kstep++) {
            int kk = w*16 + kstep*8;
            u32 A[2][4];
            #pragma unroll
            for (int m = 0; m < 2; m++) {
                A[m][0] = __float_as_uint(qs[(m*16 + g)*GST + kk + tig]);
                A[m][1] = __float_as_uint(qs[(m*16 + g + 8)*GST + kk + tig]);
                A[m][2] = __float_as_uint(qs[(m*16 + g)*GST + kk + tig + 4]);
                A[m][3] = __float_as_uint(qs[(m*16 + g + 8)*GST + kk + tig + 4]);
            }
            #pragma unroll
            for (int n = 0; n < 4; n++) {
                u32 b0 = __float_as_uint(ks[(n*8 + g)*GST + kk + tig]);
                u32 b1 = __float_as_uint(ks[(n*8 + g)*GST + kk + tig + 4]);
                mma8(D[0][n], A[0], b0, b1);
                mma8(D[1][n], A[1], b0, b1);
            }
        }
        // sumsq: warp w handles 32-px quarter of q (w<4) or k (w>=4), ch = lane
        {
            const float* srow = sq_src + lane*GST + pxq;
            #pragma unroll
            for (int p4 = 0; p4 < 32; p4 += 4) {
                float4 v = *(const float4*)(srow + p4);
                acc += v.x*v.x + v.y*v.y + v.z*v.z + v.w*v.w;
            }
        }
        __syncthreads();
    }

    ssq[w][lane] = acc;
    // S reduction: reuse sm (all mma reads done — we just passed the barrier)
    float* sred = sm;
    #pragma unroll
    for (int m = 0; m < 2; m++)
        #pragma unroll
        for (int n = 0; n < 4; n++) {
            int base = w*1024 + (m*16 + g)*32 + n*8 + 2*tig;
            sred[base]          = D[m][n][0];
            sred[base + 1]      = D[m][n][1];
            sred[base + 256]    = D[m][n][2];   // row +8 -> +8*32
            sred[base + 257]    = D[m][n][3];
        }
    __syncthreads();

    float* Sp = g_Sp + (((size_t)chunk*BB + b)*NH + h)*1024;
    #pragma unroll
    for (int it = 0; it < 4; it++) {
        int e = tid + it*256;
        float s = 0.f;
        #pragma unroll
        for (int w8 = 0; w8 < 8; w8++) s += sred[w8*1024 + e];
        Sp[e] = s;
    }
    float* sqp = g_sqp + ((size_t)chunk*BB + b)*192;
    if (tid < 32)
        sqp[h*HD + tid] = ssq[0][tid] + ssq[1][tid] + ssq[2][tid] + ssq[3][tid];
    else if (tid < 64) {
        int l = tid - 32;
        sqp[96 + h*HD + l] = ssq[4][l] + ssq[5][l] + ssq[6][l] + ssq[7][l];
    }
}

// ============ K4: normalize + relu + softmax (emits tf32-rounded A) ============
__global__ void k4_attn(const float* __restrict__ temp)
{
    int bh = blockIdx.x;
    int b = bh / NH, h = bh % NH;
    int i = threadIdx.x;
    __shared__ float nk[32];
    float sq = 0.f, sk = 0.f;
    #pragma unroll
    for (int c = 0; c < NCHUNK; c++) {
        const float* sqp = g_sqp + ((size_t)c*BB + b)*192;
        sq += sqp[h*HD + i];
        sk += sqp[96 + h*HD + i];
    }
    float nq = fmaxf(sqrtf(sq), 1e-12f);
    nk[i] = fmaxf(sqrtf(sk), 1e-12f);
    __syncwarp();
    float tp = temp[h];
    float v[32];
    float mx = 0.f;
    #pragma unroll
    for (int j = 0; j < 32; j++) {
        float s = 0.f;
        #pragma unroll
        for (int c = 0; c < NCHUNK; c++)
            s += g_Sp[(((size_t)c*BB + b)*NH + h)*1024 + i*32 + j];
        s = s / (nq * nk[j]) * tp;
        s = fmaxf(s, 0.f);
        v[j] = s;
        mx = fmaxf(mx, s);
    }
    float sum = 0.f;
    #pragma unroll
    for (int j = 0; j < 32; j++) { v[j] = expf(v[j] - mx); sum += v[j]; }
    float inv = 1.f / sum;
    #pragma unroll
    for (int j = 0; j < 32; j++)
        g_A[(size_t)bh*1024 + i*32 + j] = tf32r(v[j] * inv);
}

// ============ K5: attn@v + proj + residual + LN2 + FFN (tensor cores) ============
__global__ void __launch_bounds__(256) k5_fused(
    const float* __restrict__ x,
    const float* __restrict__ ln2w,  const float* __restrict__ ln2b,
    const float* __restrict__ projb,
    const float* __restrict__ c1b,   const float* __restrict__ c2b,
    const float* __restrict__ betac, const float* __restrict__ gamma,
    float* __restrict__ out)
{
    extern __shared__ __align__(16) float sm[];
    float* bufA = sm;               // 96*AST : v -> y -> gated g
    float* bufB = sm + 96*AST;      // 96*AST : attn_out -> yn
    int b  = blockIdx.x / NPXT;
    int p0 = (blockIdx.x % NPXT) * PXT;
    int tid = threadIdx.x;
    int w = tid >> 5, lane = tid & 31;
    int g = lane >> 2, tig = lane & 3;
    int pxw = w * 16;

    // stage 0: v tile -> bufA (tf32)
    const float* vbase = g_qkvd + ((size_t)b*C3 + 192)*HWP + p0;
    for (int idx = tid; idx < 96*PXT; idx += 256) {
        int c = idx >> 7, t = idx & 127;
        bufA[c*AST + t] = tf32r(vbase[(size_t)c*HWP + t]);
    }
    __syncthreads();

    // stage 1: attn_out = A @ v -> bufB (tf32)
    #pragma unroll 1
    for (int h = 0; h < NH; h++) {
        const float* Ab = g_A + ((size_t)b*NH + h)*1024;
        float D[2][2][4];
        #pragma unroll
        for (int m = 0; m < 2; m++)
            #pragma unroll
            for (int n = 0; n < 2; n++)
                #pragma unroll
                for (int c = 0; c < 4; c++) D[m][n][c] = 0.f;
        #pragma unroll
        for (int ksi = 0; ksi < 4; ksi++) {
            u32 b00 = __float_as_uint(bufA[(32*h + ksi*8 + tig)*AST + pxw + g]);
            u32 b01 = __float_as_uint(bufA[(32*h + ksi*8 + tig + 4)*AST + pxw + g]);
            u32 b10 = __float_as_uint(bufA[(32*h + ksi*8 + tig)*AST + pxw + 8 + g]);
            u32 b11 = __float_as_uint(bufA[(32*h + ksi*8 + tig + 4)*AST + pxw + 8 + g]);
            #pragma unroll
            for (int m = 0; m < 2; m++) {
                u32 a[4];
                int i0 = m*16 + g, j0 = ksi*8 + tig;
                a[0] = __float_as_uint(Ab[i0*32 + j0]);
                a[1] = __float_as_uint(Ab[(i0 + 8)*32 + j0]);
                a[2] = __float_as_uint(Ab[i0*32 + j0 + 4]);
                a[3] = __float_as_uint(Ab[(i0 + 8)*32 + j0 + 4]);
                mma8(D[m][0], a, b00, b01);
                mma8(D[m][1], a, b10, b11);
            }
        }
        #pragma unroll
        for (int m = 0; m < 2; m++) {
            int r0 = 32*h + m*16 + g;
            #pragma unroll
            for (int n = 0; n < 2; n++) {
                int cl = pxw + n*8 + 2*tig;
                bufB[r0*AST + cl]       = tf32r(D[m][n][0]);
                bufB[r0*AST + cl + 1]   = tf32r(D[m][n][1]);
                bufB[(r0+8)*AST + cl]   = tf32r(D[m][n][2]);
                bufB[(r0+8)*AST + cl+1] = tf32r(D[m][n][3]);
            }
        }
    }
    __syncthreads();

    // stage 2: y = x + (proj(attn_out)+pb)*betac -> bufA (fp32) + yreg
    float yreg[48];
    #pragma unroll 1
    for (int mtp = 0; mtp < 3; mtp++) {
        float D[2][2][4];
        #pragma unroll
        for (int m = 0; m < 2; m++)
            #pragma unroll
            for (int n = 0; n < 2; n++)
                #pragma unroll
                for (int c = 0; c < 4; c++) D[m][n][c] = 0.f;
        #pragma unroll 2
        for (int ksi = 0; ksi < 12; ksi++) {
            u32 A0[4], A1[4];
            ldA(A0, g_pk_proj, (2*mtp)*12 + ksi, lane);
            ldA(A1, g_pk_proj, (2*mtp + 1)*12 + ksi, lane);
            u32 b00 = __float_as_uint(bufB[(ksi*8 + tig)*AST + pxw + g]);
            u32 b01 = __float_as_uint(bufB[(ksi*8 + tig + 4)*AST + pxw + g]);
            u32 b10 = __float_as_uint(bufB[(ksi*8 + tig)*AST + pxw + 8 + g]);
            u32 b11 = __float_as_uint(bufB[(ksi*8 + tig + 4)*AST + pxw + 8 + g]);
            mma8(D[0][0], A0, b00, b01); mma8(D[0][1], A0, b10, b11);
            mma8(D[1][0], A1, b00, b01); mma8(D[1][1], A1, b10, b11);
        }
        #pragma unroll
        for (int m = 0; m < 2; m++) {
            int r0 = (2*mtp + m)*16 + g;
            float pb0 = projb[r0], bc0 = betac[r0];
            float pb1 = projb[r0 + 8], bc1 = betac[r0 + 8];
            #pragma unroll
            for (int n = 0; n < 2; n++) {
                int cl = pxw + n*8 + 2*tig;
                float2 xv0 = *(const float2*)(x + ((size_t)b*CC + r0)*HWP + p0 + cl);
                float2 xv1 = *(const float2*)(x + ((size_t)b*CC + r0 + 8)*HWP + p0 + cl);
                float y0 = xv0.x + (D[m][n][0] + pb0)*bc0;
                float y1 = xv0.y + (D[m][n][1] + pb0)*bc0;
                float y2 = xv1.x + (D[m][n][2] + pb1)*bc1;
                float y3 = xv1.y + (D[m][n][3] + pb1)*bc1;
                int yi = ((mtp*2 + m)*2 + n)*4;
                yreg[yi] = y0; yreg[yi+1] = y1; yreg[yi+2] = y2; yreg[yi+3] = y3;
                bufA[r0*AST + cl] = y0;       bufA[r0*AST + cl + 1] = y1;
                bufA[(r0+8)*AST + cl] = y2;   bufA[(r0+8)*AST + cl + 1] = y3;
            }
        }
    }
    __syncthreads();

    // stage 3: LN2(bufA) -> bufB (tf32)
    if (tid < PXT) {
        float s = 0.f, s2 = 0.f;
        #pragma unroll
        for (int c = 0; c < 96; c++) { float v = bufA[c*AST + tid]; s += v; s2 += v*v; }
        float mu  = s * (1.0f/96.0f);
        float var = fmaxf(s2 * (1.0f/96.0f) - mu*mu, 0.f);
        float rs  = rsqrtf(var + 1e-6f);
        #pragma unroll
        for (int c = 0; c < 96; c++) {
            float v = bufA[c*AST + tid];
            bufB[c*AST + tid] = tf32r((v - mu) * rs * ln2w[c] + ln2b[c]);
        }
    }
    __syncthreads();

    // stage 4: g = (conv1a(yn)+b1)*(conv1b(yn)+b2) -> bufA (tf32)
    #pragma unroll 1
    for (int mtp = 0; mtp < 3; mtp++) {
        float D1[2][2][4], D2[2][2][4];
        #pragma unroll
        for (int m = 0; m < 2; m++)
            #pragma unroll
            for (int n = 0; n < 2; n++)
                #pragma unroll
                for (int c = 0; c < 4; c++) { D1[m][n][c] = 0.f; D2[m][n][c] = 0.f; }
        #pragma unroll 1
        for (int ksi = 0; ksi < 12; ksi++) {
            u32 A0[4], A1[4], A2[4], A3[4];
            ldA(A0, g_pk_c1, (2*mtp)*12 + ksi, lane);
            ldA(A1, g_pk_c1, (2*mtp + 1)*12 + ksi, lane);
            ldA(A2, g_pk_c1, (2*mtp + 6)*12 + ksi, lane);
            ldA(A3, g_pk_c1, (2*mtp + 7)*12 + ksi, lane);
            u32 b00 = __float_as_uint(bufB[(ksi*8 + tig)*AST + pxw + g]);
            u32 b01 = __float_as_uint(bufB[(ksi*8 + tig + 4)*AST + pxw + g]);
            u32 b10 = __float_as_uint(bufB[(ksi*8 + tig)*AST + pxw + 8 + g]);
            u32 b11 = __float_as_uint(bufB[(ksi*8 + tig + 4)*AST + pxw + 8 + g]);
            mma8(D1[0][0], A0, b00, b01); mma8(D1[0][1], A0, b10, b11);
            mma8(D1[1][0], A1, b00, b01); mma8(D1[1][1], A1, b10, b11);
            mma8(D2[0][0], A2, b00, b01); mma8(D2[0][1], A2, b10, b11);
            mma8(D2[1][0], A3, b00, b01); mma8(D2[1][1], A3, b10, b11);
        }
        #pragma unroll
        for (int m = 0; m < 2; m++) {
            int r0 = (2*mtp + m)*16 + g;
            float ba0 = c1b[r0], bb0 = c1b[96 + r0];
            float ba1 = c1b[r0 + 8], bb1 = c1b[96 + r0 + 8];
            #pragma unroll
            for (int n = 0; n < 2; n++) {
                int cl = pxw + n*8 + 2*tig;
                bufA[r0*AST + cl]       = tf32r((D1[m][n][0] + ba0)*(D2[m][n][0] + bb0));
                bufA[r0*AST + cl + 1]   = tf32r((D1[m][n][1] + ba0)*(D2[m][n][1] + bb0));
                bufA[(r0+8)*AST + cl]   = tf32r((D1[m][n][2] + ba1)*(D2[m][n][2] + bb1));
                bufA[(r0+8)*AST + cl+1] = tf32r((D1[m][n][3] + ba1)*(D2[m][n][3] + bb1));
            }
        }
    }
    __syncthreads();

    // stage 5: out = y + (conv2(g)+cb)*gamma
    #pragma unroll 1
    for (int mtp = 0; mtp < 3; mtp++) {
        float D[2][2][4];
        #pragma unroll
        for (int m = 0; m < 2; m++)
            #pragma unroll
            for (int n = 0; n < 2; n++)
                #pragma unroll
                for (int c = 0; c < 4; c++) D[m][n][c] = 0.f;
        #pragma unroll 2
        for (int ksi = 0; ksi < 12; ksi++) {
            u32 A0[4], A1[4];
            ldA(A0, g_pk_c2, (2*mtp)*12 + ksi, lane);
            ldA(A1, g_pk_c2, (2*mtp + 1)*12 + ksi, lane);
            u32 b00 = __float_as_uint(bufA[(ksi*8 + tig)*AST + pxw + g]);
            u32 b01 = __float_as_uint(bufA[(ksi*8 + tig + 4)*AST + pxw + g]);
            u32 b10 = __float_as_uint(bufA[(ksi*8 + tig)*AST + pxw + 8 + g]);
            u32 b11 = __float_as_uint(bufA[(ksi*8 + tig + 4)*AST + pxw + 8 + g]);
            mma8(D[0][0], A0, b00, b01); mma8(D[0][1], A0, b10, b11);
            mma8(D[1][0], A1, b00, b01); mma8(D[1][1], A1, b10, b11);
        }
        #pragma unroll
        for (int m = 0; m < 2; m++) {
            int r0 = (2*mtp + m)*16 + g;
            float cb0 = c2b[r0], gm0 = gamma[r0];
            float cb1 = c2b[r0 + 8], gm1 = gamma[r0 + 8];
            #pragma unroll
            for (int n = 0; n < 2; n++) {
                int cl = pxw + n*8 + 2*tig;
                int yi = ((mtp*2 + m)*2 + n)*4;
                float2 o0, o1;
                o0.x = yreg[yi]   + (D[m][n][0] + cb0)*gm0;
                o0.y = yreg[yi+1] + (D[m][n][1] + cb0)*gm0;
                o1.x = yreg[yi+2] + (D[m][n][2] + cb1)*gm1;
                o1.y = yreg[yi+3] + (D[m][n][3] + cb1)*gm1;
                *(float2*)(out + ((size_t)b*CC + r0)*HWP + p0 + cl) = o0;
                *(float2*)(out + ((size_t)b*CC + r0 + 8)*HWP + p0 + cl) = o1;
            }
        }
    }
}

extern "C" void kernel_launch(void* const* d_in, const int* in_sizes, int n_in,
                              void* d_out, int out_size) {
    (void)in_sizes; (void)n_in; (void)out_size;
    const float* x      = (const float*)d_in[0];
    const float* ln1_w  = (const float*)d_in[1];
    const float* ln1_b  = (const float*)d_in[2];
    const float* ln2_w  = (const float*)d_in[3];
    const float* ln2_b  = (const float*)d_in[4];
    const float* qkv_w  = (const float*)d_in[5];
    const float* qkv_b  = (const float*)d_in[6];
    const float* dw_w   = (const float*)d_in[7];
    const float* dw_b   = (const float*)d_in[8];
    const float* temp   = (const float*)d_in[9];
    const float* proj_w = (const float*)d_in[10];
    const float* proj_b = (const float*)d_in[11];
    const float* c1_w   = (const float*)d_in[12];
    const float* c1_b   = (const float*)d_in[13];
    const float* c2_w   = (const float*)d_in[14];
    const float* c2_b   = (const float*)d_in[15];
    const float* betac  = (const float*)d_in[16];
    const float* gamma  = (const float*)d_in[17];
    float* out = (float*)d_out;

    cudaFuncSetAttribute(k1_ln_qkv, cudaFuncAttributeMaxDynamicSharedMemorySize, 96*AST*4);
    cudaFuncSetAttribute(k5_fused,  cudaFuncAttributeMaxDynamicSharedMemorySize, 2*96*AST*4);

    k0_pack<<<252, 256>>>(qkv_w, proj_w, c1_w, c2_w);
    k1_ln_qkv<<<BB*NPXT, 256, 96*AST*4>>>(x, ln1_w, ln1_b, qkv_b);
    k2_dw<<<dim3(BB*C3, HH/8), 192>>>(dw_w, dw_b);
    k3_gram<<<dim3(BB*NH, NCHUNK), 256>>>();
    k4_attn<<<BB*NH, 32>>>(temp);
    k5_fused<<<BB*NPXT, 256, 2*96*AST*4>>>(x, ln2_w, ln2_b, proj_b,
                                           c1_b, c2_b, betac, gamma, out);
}